// round 2
// baseline (speedup 1.0000x reference)
#include <cuda_runtime.h>
#include <cuda_bf16.h>

// NHConv: out[b,n,o] = sum_{k,f} x[b, adjc[n,k], f] * W[k,f,o] + bias[o]
// B=2, N=196608, K=9, F_IN=F_OUT=64.
// Gather-GEMM: M = B*N rows, K' = 9*64 = 576, N' = 64.
// CTA: 64-row tile x 64 outputs, 256 threads, 4x4 register tile per thread.
// adjc is int32 on device (JAX x64 disabled downcasts the int64 request).

#define TILE_M   64
#define FDIM     64
#define KNBR     9
#define NTHREADS 256

__global__ __launch_bounds__(NTHREADS, 4)
void nhconv_kernel(const float* __restrict__ x,
                   const int* __restrict__ adjc,
                   const float* __restrict__ W,
                   const float* __restrict__ bias,
                   float* __restrict__ out,
                   int Nn)
{
    __shared__ float As[FDIM][TILE_M];  // As[f][row]  (16 KB)
    __shared__ float Ws[FDIM][FDIM];    // Ws[f][o]    (16 KB)

    const int tid = threadIdx.x;

    // global row range for this CTA: [m0, m0+64). N % 64 == 0 so one batch per tile.
    const long long m0 = (long long)blockIdx.x * TILE_M;
    const int b  = (int)(m0 / Nn);
    const int n0 = (int)(m0 - (long long)b * Nn);
    const float* xb = x + (long long)b * Nn * FDIM;

    // compute-phase thread tile: rowg = tid/16 (0..15), colg = tid%16 (0..15)
    const int rowg = tid >> 4;
    const int colg = tid & 15;

    // load-phase roles: lrow = tid & 63 (row within tile), lf = 16-wide f chunk
    const int lrow = tid & 63;
    const int lf   = (tid >> 6) * 16;

    float acc[4][4];
#pragma unroll
    for (int i = 0; i < 4; i++)
#pragma unroll
        for (int j = 0; j < 4; j++) acc[i][j] = 0.0f;

    for (int k = 0; k < KNBR; k++) {
        // ---- gather A tile: 64 rows of x[b, adjc[n0+lrow, k], :] ----
        const int nb = adjc[(long long)(n0 + lrow) * KNBR + k];
        const float4* asrc = reinterpret_cast<const float4*>(xb + (long long)nb * FDIM + lf);
#pragma unroll
        for (int v = 0; v < 4; v++) {
            float4 val = asrc[v];
            int f = lf + v * 4;
            As[f + 0][lrow] = val.x;
            As[f + 1][lrow] = val.y;
            As[f + 2][lrow] = val.z;
            As[f + 3][lrow] = val.w;
        }

        // ---- load W[k] (64x64 fp32 = 16 KB), already [f][o] layout ----
        const float4* wsrc = reinterpret_cast<const float4*>(W + k * FDIM * FDIM);
        float4* wdst = reinterpret_cast<float4*>(&Ws[0][0]);
#pragma unroll
        for (int v = 0; v < 4; v++)
            wdst[tid + v * NTHREADS] = wsrc[tid + v * NTHREADS];

        __syncthreads();

        // ---- inner product over f: 2x LDS.128 + 16 FFMA per step ----
#pragma unroll 16
        for (int f = 0; f < FDIM; f++) {
            float4 a = *reinterpret_cast<const float4*>(&As[f][rowg * 4]);
            float4 w = *reinterpret_cast<const float4*>(&Ws[f][colg * 4]);
            acc[0][0] += a.x * w.x; acc[0][1] += a.x * w.y;
            acc[0][2] += a.x * w.z; acc[0][3] += a.x * w.w;
            acc[1][0] += a.y * w.x; acc[1][1] += a.y * w.y;
            acc[1][2] += a.y * w.z; acc[1][3] += a.y * w.w;
            acc[2][0] += a.z * w.x; acc[2][1] += a.z * w.y;
            acc[2][2] += a.z * w.z; acc[2][3] += a.z * w.w;
            acc[3][0] += a.w * w.x; acc[3][1] += a.w * w.y;
            acc[3][2] += a.w * w.z; acc[3][3] += a.w * w.w;
        }

        __syncthreads();
    }

    // ---- epilogue: add bias, store float4 per row ----
    const float4 bv = *reinterpret_cast<const float4*>(bias + colg * 4);
#pragma unroll
    for (int i = 0; i < 4; i++) {
        long long row = m0 + rowg * 4 + i;
        float4 o;
        o.x = acc[i][0] + bv.x;
        o.y = acc[i][1] + bv.y;
        o.z = acc[i][2] + bv.z;
        o.w = acc[i][3] + bv.w;
        *reinterpret_cast<float4*>(out + row * FDIM + colg * 4) = o;
    }
}

extern "C" void kernel_launch(void* const* d_in, const int* in_sizes, int n_in,
                              void* d_out, int out_size)
{
    const float* x    = (const float*)d_in[0];   // (B, N, 64) fp32
    const int*   adjc = (const int*)d_in[1];     // (N, 9) int32 (x64-disabled JAX)
    const float* W    = (const float*)d_in[2];   // (9, 64, 64) fp32
    const float* bias = (const float*)d_in[3];   // (64,) fp32
    float*       out  = (float*)d_out;           // (B, N, 64) fp32

    const int adj_elems = in_sizes[1];           // N * 9
    const int Nn        = adj_elems / KNBR;      // 196608
    const long long M   = (long long)out_size / FDIM;  // B * N rows

    const int grid = (int)(M / TILE_M);          // 6144
    nhconv_kernel<<<grid, NTHREADS>>>(x, adjc, W, bias, out, Nn);
}

// round 4
// speedup vs baseline: 4.7360x; 4.7360x over previous
#include <cuda_runtime.h>
#include <cstdint>

// NHConv via warp-level tf32 mma.sync (m16n8k8) gather-GEMM.
// out[b,n,o] = sum_{k,f} x[b, adjc[n,k], f] * W[k,f,o] + bias[o]
// Persistent CTAs; all 9 W tiles resident in smem (transposed, padded stride 68
// -> conflict-free B-fragment LDS). A gathered straight into mma fragment regs
// (no A smem, no syncthreads in the k loop). Warp tile: 32 rows x 64 cols.

#define KNBR     9
#define FDIM     64
#define TILE_M   256
#define NTHREADS 256
#define WSTRIDE  68   // floats per W row (o-major rows of length FDIM, padded)

__device__ float g_Wt[KNBR * FDIM * FDIM];   // [k][o][f], tf32-RN-rounded

// ---- prep: Wt[k][o][f] = round_tf32_rn(W[k][f][o]) ----
__global__ void prep_W(const float* __restrict__ W) {
    int idx = blockIdx.x * 256 + threadIdx.x;
    if (idx >= KNBR * FDIM * FDIM) return;
    int k = idx >> 12, rem = idx & 4095, o = rem >> 6, f = rem & 63;
    float v = W[(k << 12) + (f << 6) + o];
    uint32_t t;
    asm("cvt.rna.tf32.f32 %0, %1;" : "=r"(t) : "f"(v));
    g_Wt[idx] = __uint_as_float(t);
}

static __device__ __forceinline__ uint32_t f2tf32(float v) {
    uint32_t t;
    asm("cvt.rna.tf32.f32 %0, %1;" : "=r"(t) : "f"(v));
    return t;
}

static __device__ __forceinline__ void mma_tf32(float* c, const uint32_t* a,
                                                uint32_t b0, uint32_t b1) {
    asm volatile(
        "mma.sync.aligned.m16n8k8.row.col.f32.tf32.tf32.f32 "
        "{%0,%1,%2,%3}, {%4,%5,%6,%7}, {%8,%9}, {%0,%1,%2,%3};"
        : "+f"(c[0]), "+f"(c[1]), "+f"(c[2]), "+f"(c[3])
        : "r"(a[0]), "r"(a[1]), "r"(a[2]), "r"(a[3]), "r"(b0), "r"(b1));
}

// load A fragments for 4 k-steps (s = S0..S0+3) for both m16 tiles of this warp
static __device__ __forceinline__ void load_a(uint32_t a[4][2][4],
                                              const float* __restrict__ xb,
                                              const int* ix, int S0, int tig) {
#pragma unroll
    for (int t = 0; t < 2; t++) {
        const float* p0 = xb + (size_t)ix[2 * t] * FDIM;       // rows g+16t
        const float* p1 = xb + (size_t)ix[2 * t + 1] * FDIM;   // rows g+8+16t
#pragma unroll
        for (int sl = 0; sl < 4; sl++) {
            int f = (S0 + sl) * 8 + tig;
            float v0 = p0[f], v2 = p0[f + 4];
            float v1 = p1[f], v3 = p1[f + 4];
            a[sl][t][0] = f2tf32(v0);
            a[sl][t][1] = f2tf32(v1);
            a[sl][t][2] = f2tf32(v2);
            a[sl][t][3] = f2tf32(v3);
        }
    }
}

static __device__ __forceinline__ void mma_group(float acc[2][8][4],
                                                 const uint32_t a[4][2][4],
                                                 const float* wk, int S0,
                                                 int g, int tig) {
#pragma unroll
    for (int sl = 0; sl < 4; sl++) {
        int f = (S0 + sl) * 8 + tig;
#pragma unroll
        for (int j = 0; j < 8; j++) {
            const float* wp = wk + (8 * j + g) * WSTRIDE + f;
            uint32_t b0 = __float_as_uint(wp[0]);
            uint32_t b1 = __float_as_uint(wp[4]);
            mma_tf32(acc[0][j], a[sl][0], b0, b1);
            mma_tf32(acc[1][j], a[sl][1], b0, b1);
        }
    }
}

__global__ __launch_bounds__(NTHREADS, 1)
void nhconv_mma(const float* __restrict__ x,
                const int* __restrict__ adjc,
                const float* __restrict__ bias,
                float* __restrict__ out,
                int Nn, int ntile)
{
    extern __shared__ float Wts[];   // [k][o][WSTRIDE]

    // stage all 9 W tiles once (float4, conflict-free STS)
    for (int q = threadIdx.x; q < KNBR * FDIM * 16; q += NTHREADS) {
        int k = q >> 10, o = (q >> 4) & 63, fq = q & 15;
        float4 v = reinterpret_cast<const float4*>(g_Wt)[q];
        *reinterpret_cast<float4*>(&Wts[(k * FDIM + o) * WSTRIDE + fq * 4]) = v;
    }
    __syncthreads();

    const int tid  = threadIdx.x;
    const int lane = tid & 31;
    const int w    = tid >> 5;
    const int g    = lane >> 2;    // 0..7
    const int tig  = lane & 3;     // 0..3

    float acc[2][8][4];
#pragma unroll
    for (int t = 0; t < 2; t++)
#pragma unroll
        for (int j = 0; j < 8; j++)
#pragma unroll
            for (int r = 0; r < 4; r++) acc[t][j][r] = 0.0f;

    for (int tile = blockIdx.x; tile < ntile; tile += gridDim.x) {
        const long long m0 = (long long)tile * TILE_M;
        const int b  = (int)(m0 / Nn);
        const int n0 = (int)(m0 - (long long)b * Nn);
        const float* xb = x + (long long)b * Nn * FDIM;
        const int rb = n0 + w * 32 + g;          // rows rb + 8i, i=0..3

        int ixc[4], ixn[4];
#pragma unroll
        for (int i = 0; i < 4; i++) ixc[i] = adjc[(rb + 8 * i) * KNBR];

        uint32_t aA[4][2][4], aB[4][2][4];
        load_a(aA, xb, ixc, 0, tig);

#pragma unroll 1
        for (int k = 0; k < KNBR; k++) {
            const float* wk = &Wts[k * FDIM * WSTRIDE];
            if (k + 1 < KNBR) {
#pragma unroll
                for (int i = 0; i < 4; i++)
                    ixn[i] = adjc[(rb + 8 * i) * KNBR + k + 1];
            }
            load_a(aB, xb, ixc, 4, tig);          // second half of k
            mma_group(acc, aA, wk, 0, g, tig);
            if (k + 1 < KNBR) load_a(aA, xb, ixn, 0, tig);  // first half of k+1
            mma_group(acc, aB, wk, 4, g, tig);
#pragma unroll
            for (int i = 0; i < 4; i++) ixc[i] = ixn[i];
        }

        // epilogue: bias + store, then zero acc for next tile
        const long long mrow = m0 + w * 32 + g;
#pragma unroll
        for (int t = 0; t < 2; t++) {
#pragma unroll
            for (int j = 0; j < 8; j++) {
                int col = 8 * j + 2 * tig;
                float2 bv = *reinterpret_cast<const float2*>(bias + col);
                float2 o0 = { acc[t][j][0] + bv.x, acc[t][j][1] + bv.y };
                float2 o1 = { acc[t][j][2] + bv.x, acc[t][j][3] + bv.y };
                *reinterpret_cast<float2*>(out + (mrow + 16 * t) * FDIM + col) = o0;
                *reinterpret_cast<float2*>(out + (mrow + 16 * t + 8) * FDIM + col) = o1;
                acc[t][j][0] = 0.f; acc[t][j][1] = 0.f;
                acc[t][j][2] = 0.f; acc[t][j][3] = 0.f;
            }
        }
    }
}

extern "C" void kernel_launch(void* const* d_in, const int* in_sizes, int n_in,
                              void* d_out, int out_size)
{
    const float* x    = (const float*)d_in[0];   // (B, N, 64) fp32
    const int*   adjc = (const int*)d_in[1];     // (N, 9) int32
    const float* W    = (const float*)d_in[2];   // (9, 64, 64) fp32
    const float* bias = (const float*)d_in[3];   // (64,) fp32
    float*       out  = (float*)d_out;

    const int Nn = in_sizes[1] / KNBR;
    const long long M = (long long)out_size / FDIM;
    const int ntile = (int)(M / TILE_M);          // 1536

    const int smem = KNBR * FDIM * WSTRIDE * 4;   // 156,672 B
    cudaFuncSetAttribute(nhconv_mma, cudaFuncAttributeMaxDynamicSharedMemorySize, smem);

    int nsm = 148;
    cudaDeviceGetAttribute(&nsm, cudaDevAttrMultiProcessorCount, 0);
    const int grid = (ntile < nsm) ? ntile : nsm;

    prep_W<<<(KNBR * FDIM * FDIM + 255) / 256, 256>>>(W);
    nhconv_mma<<<grid, NTHREADS, smem>>>(x, adjc, bias, out, Nn, ntile);
}

// round 5
// speedup vs baseline: 5.7835x; 1.2212x over previous
#include <cuda_runtime.h>
#include <cstdint>

// NHConv via tf32 mma.sync m16n8k8, coalesced gather + ldmatrix fragments.
// out[b,n,o] = sum_{k,f} x[b, adjc[n,k], f] * W[k,f,o] + bias[o]
// Per warp: 32 M-rows x 64 N-cols, K' = 576. A gathered coalesced into a
// per-warp swizzled smem buffer (ping/pong 4KB half-k stages), fragments via
// ldmatrix.x4. W (tf32-rounded, transposed [k][o][f]) resident in smem,
// B fragments via ldmatrix.x4 (two n-tiles per instruction). Persistent grid.

#define KNBR   9
#define FDIM   64
#define WROWS  32
#define WARPS  8
#define NTHREADS 256

#define W_BYTES (KNBR * FDIM * FDIM * 4)          // 147456
#define ABUF    8192                               // per-warp, 2 x 4KB stages
#define SMEM_TOTAL (W_BYTES + WARPS * ABUF)        // 212992

__device__ float g_Wt[KNBR * FDIM * FDIM];         // [k][o][f], tf32-RN

// ---- prep: Wt[k][o][f] = round_tf32_rn(W[k][f][o]) ----
__global__ void prep_W(const float* __restrict__ W) {
    int idx = blockIdx.x * 256 + threadIdx.x;
    if (idx >= KNBR * FDIM * FDIM) return;
    int k = idx >> 12, rem = idx & 4095, o = rem >> 6, f = rem & 63;
    float v = W[(k << 12) + (f << 6) + o];
    uint32_t t;
    asm("cvt.rna.tf32.f32 %0, %1;" : "=r"(t) : "f"(v));
    g_Wt[idx] = __uint_as_float(t);
}

static __device__ __forceinline__ uint32_t f2tf32(float v) {
    uint32_t t;
    asm("cvt.rna.tf32.f32 %0, %1;" : "=r"(t) : "f"(v));
    return t;
}
static __device__ __forceinline__ uint32_t smem_u32(const void* p) {
    uint32_t a;
    asm("{ .reg .u64 t; cvta.to.shared.u64 t, %1; cvt.u32.u64 %0, t; }" : "=r"(a) : "l"(p));
    return a;
}

#define LDSM4(r, addr)                                                          \
    asm volatile("ldmatrix.sync.aligned.m8n8.x4.shared.b16 {%0,%1,%2,%3}, [%4];" \
        : "=r"((r)[0]), "=r"((r)[1]), "=r"((r)[2]), "=r"((r)[3]) : "r"(addr))

static __device__ __forceinline__ void mma_tf32(float* c, uint32_t a0, uint32_t a1,
                                                uint32_t a2, uint32_t a3,
                                                uint32_t b0, uint32_t b1) {
    asm volatile(
        "mma.sync.aligned.m16n8k8.row.col.f32.tf32.tf32.f32 "
        "{%0,%1,%2,%3}, {%4,%5,%6,%7}, {%8,%9}, {%0,%1,%2,%3};"
        : "+f"(c[0]), "+f"(c[1]), "+f"(c[2]), "+f"(c[3])
        : "r"(a0), "r"(a1), "r"(a2), "r"(a3), "r"(b0), "r"(b1));
}

__global__ __launch_bounds__(NTHREADS, 1)
void nhconv_ldsm(const float* __restrict__ x,
                 const int* __restrict__ adjc,
                 const float* __restrict__ bias,
                 float* __restrict__ out,
                 int Nn, int nwt)
{
    extern __shared__ char smem[];
    const uint32_t sbase = smem_u32(smem);
    const int tid  = threadIdx.x;
    const int lane = tid & 31;
    const int w    = tid >> 5;

    // ---- stage all 9 W tiles, swizzled: byte = k*16384 + o*256 + ((c^(o&7))<<4)
    for (int q = tid; q < KNBR * FDIM * 16; q += NTHREADS) {
        int k = q >> 10, o = (q >> 4) & 63, c = q & 15;
        float4 v = reinterpret_cast<const float4*>(g_Wt)[q];
        *reinterpret_cast<float4*>(smem + k * 16384 + o * 256 + ((c ^ (o & 7)) << 4)) = v;
    }
    __syncthreads();

    const uint32_t wB   = sbase;                    // W base
    const uint32_t wbuf = sbase + W_BYTES + w * ABUF;

    // gather-role constants: lane covers granule lr8 of rows rq+4i
    const int lr8 = lane & 7;
    const int rq  = lane >> 3;
    const uint32_t swz0 = (uint32_t)((lr8 ^ rq) << 4);
    const uint32_t swz1 = (uint32_t)((lr8 ^ (rq + 4)) << 4);

    // ldmatrix-role constants
    const int lr      = lane & 7;
    const int grp     = lane >> 3;          // 0..3
    const int halfsel = grp & 1;            // +16B
    const int rhi     = (grp >> 1) << 3;    // +8 rows
    const uint32_t rowAbyte = (uint32_t)((rhi + lr) * 128);
    const uint32_t rowBbyte = (uint32_t)((rhi + lr) * 256);
    uint32_t gA[4], gB[8];
#pragma unroll
    for (int s = 0; s < 4; s++) gA[s] = (uint32_t)(((2 * s + halfsel) ^ lr) << 4);
#pragma unroll
    for (int s = 0; s < 8; s++) gB[s] = (uint32_t)(((2 * s + halfsel) ^ lr) << 4);

    // bias fragment: cols 8j + 2*(lane&3)
    const int tig = lane & 3;
    float2 bj[8];
#pragma unroll
    for (int j = 0; j < 8; j++)
        bj[j] = *reinterpret_cast<const float2*>(bias + 8 * j + 2 * tig);

    float acc[2][8][4];
#pragma unroll
    for (int t = 0; t < 2; t++)
#pragma unroll
        for (int j = 0; j < 8; j++)
#pragma unroll
            for (int r = 0; r < 4; r++) acc[t][j][r] = 0.0f;

    const int gw      = blockIdx.x * WARPS + w;
    const int wstride = gridDim.x * WARPS;

    for (int wt = gw; wt < nwt; wt += wstride) {
        const long long m0 = (long long)wt * WROWS;
        const int b  = (int)(m0 / Nn);
        const int n0 = (int)(m0 - (long long)b * Nn);
        const float* xb = x + (size_t)b * Nn * FDIM;
        const int* arow = adjc + (size_t)n0 * KNBR;

        int idx[8];
#pragma unroll
        for (int i = 0; i < 8; i++) idx[i] = arow[(rq + 4 * i) * KNBR];
        float4 G[8];
#pragma unroll
        for (int i = 0; i < 8; i++)
            G[i] = *reinterpret_cast<const float4*>(xb + (size_t)idx[i] * FDIM + lr8 * 4);

        int p = 0;
#pragma unroll 1
        for (int k = 0; k < KNBR; k++) {
            const uint32_t wk = wB + k * 16384;
#pragma unroll
            for (int h = 0; h < 2; h++) {
                const uint32_t stage = wbuf + p * 4096;
                // round + store stage
#pragma unroll
                for (int i = 0; i < 8; i++) {
                    uint32_t r0 = f2tf32(G[i].x), r1 = f2tf32(G[i].y);
                    uint32_t r2 = f2tf32(G[i].z), r3 = f2tf32(G[i].w);
                    uint32_t a = stage + (rq + 4 * i) * 128 + ((i & 1) ? swz1 : swz0);
                    asm volatile("st.shared.v4.b32 [%0], {%1,%2,%3,%4};"
                        :: "r"(a), "r"(r0), "r"(r1), "r"(r2), "r"(r3) : "memory");
                }
                __syncwarp();

                // prefetch next half-stage
                if (h == 0) {
#pragma unroll
                    for (int i = 0; i < 8; i++)
                        G[i] = *reinterpret_cast<const float4*>(
                            xb + (size_t)idx[i] * FDIM + 32 + lr8 * 4);
                } else if (k < KNBR - 1) {
#pragma unroll
                    for (int i = 0; i < 8; i++) idx[i] = arow[(rq + 4 * i) * KNBR + k + 1];
#pragma unroll
                    for (int i = 0; i < 8; i++)
                        G[i] = *reinterpret_cast<const float4*>(
                            xb + (size_t)idx[i] * FDIM + lr8 * 4);
                }

                // compute 4 k-steps on stage
#pragma unroll
                for (int sl = 0; sl < 4; sl++) {
                    const int s = h * 4 + sl;
                    uint32_t rA0[4], rA1[4];
                    LDSM4(rA0, stage + rowAbyte + gA[sl]);
                    LDSM4(rA1, stage + 2048 + rowAbyte + gA[sl]);
#pragma unroll
                    for (int pq = 0; pq < 4; pq++) {
                        uint32_t rBv[4];
                        LDSM4(rBv, wk + pq * 4096 + rowBbyte + gB[s]);
                        mma_tf32(acc[0][2 * pq],     rA0[0], rA0[2], rA0[1], rA0[3], rBv[0], rBv[1]);
                        mma_tf32(acc[1][2 * pq],     rA1[0], rA1[2], rA1[1], rA1[3], rBv[0], rBv[1]);
                        mma_tf32(acc[0][2 * pq + 1], rA0[0], rA0[2], rA0[1], rA0[3], rBv[2], rBv[3]);
                        mma_tf32(acc[1][2 * pq + 1], rA1[0], rA1[2], rA1[1], rA1[3], rBv[2], rBv[3]);
                    }
                }
                p ^= 1;
            }
        }

        // epilogue: bias + store, zero acc
        const int g = lane >> 2;
#pragma unroll
        for (int t = 0; t < 2; t++) {
            float* r0 = out + (size_t)(m0 + t * 16 + g) * FDIM;
            float* r1 = r0 + 8 * FDIM;
#pragma unroll
            for (int j = 0; j < 8; j++) {
                int col = 8 * j + 2 * tig;
                float2 o0 = { acc[t][j][0] + bj[j].x, acc[t][j][1] + bj[j].y };
                float2 o1 = { acc[t][j][2] + bj[j].x, acc[t][j][3] + bj[j].y };
                *reinterpret_cast<float2*>(r0 + col) = o0;
                *reinterpret_cast<float2*>(r1 + col) = o1;
                acc[t][j][0] = 0.f; acc[t][j][1] = 0.f;
                acc[t][j][2] = 0.f; acc[t][j][3] = 0.f;
            }
        }
    }
}

extern "C" void kernel_launch(void* const* d_in, const int* in_sizes, int n_in,
                              void* d_out, int out_size)
{
    const float* x    = (const float*)d_in[0];   // (B, N, 64) fp32
    const int*   adjc = (const int*)d_in[1];     // (N, 9) int32
    const float* W    = (const float*)d_in[2];   // (9, 64, 64) fp32
    const float* bias = (const float*)d_in[3];   // (64,) fp32
    float*       out  = (float*)d_out;

    const int Nn = in_sizes[1] / KNBR;
    const long long M = (long long)out_size / FDIM;
    const int nwt = (int)(M / WROWS);            // 12288 warp-tiles

    cudaFuncSetAttribute(nhconv_ldsm, cudaFuncAttributeMaxDynamicSharedMemorySize, SMEM_TOTAL);

    int nsm = 148;
    cudaDeviceGetAttribute(&nsm, cudaDevAttrMultiProcessorCount, 0);

    prep_W<<<(KNBR * FDIM * FDIM + 255) / 256, 256>>>(W);
    nhconv_ldsm<<<nsm, NTHREADS, SMEM_TOTAL>>>(x, adjc, bias, out, Nn, nwt);
}

// round 6
// speedup vs baseline: 6.3194x; 1.0927x over previous
#include <cuda_runtime.h>
#include <cstdint>

// NHConv via tf32 mma.sync m16n8k8, coalesced gather + ldmatrix fragments.
// out[b,n,o] = sum_{k,f} x[b, adjc[n,k], f] * W[k,f,o] + bias[o]
// A is used UNROUNDED (mma tf32 truncates mantissa in HW); W is RN-pre-rounded
// by prep kernel. Per warp: 32 M-rows x 64 N-cols, K' = 576, ping/pong smem
// staging, persistent grid.

#define KNBR   9
#define FDIM   64
#define WROWS  32
#define WARPS  8
#define NTHREADS 256

#define W_BYTES (KNBR * FDIM * FDIM * 4)          // 147456
#define ABUF    8192                               // per-warp, 2 x 4KB stages
#define SMEM_TOTAL (W_BYTES + WARPS * ABUF)        // 212992

__device__ float g_Wt[KNBR * FDIM * FDIM];         // [k][o][f], tf32-RN

// ---- prep: Wt[k][o][f] = round_tf32_rn(W[k][f][o]) ----
__global__ void prep_W(const float* __restrict__ W) {
    int idx = blockIdx.x * 256 + threadIdx.x;
    if (idx >= KNBR * FDIM * FDIM) return;
    int k = idx >> 12, rem = idx & 4095, o = rem >> 6, f = rem & 63;
    float v = W[(k << 12) + (f << 6) + o];
    uint32_t t;
    asm("cvt.rna.tf32.f32 %0, %1;" : "=r"(t) : "f"(v));
    g_Wt[idx] = __uint_as_float(t);
}

static __device__ __forceinline__ uint32_t smem_u32(const void* p) {
    uint32_t a;
    asm("{ .reg .u64 t; cvta.to.shared.u64 t, %1; cvt.u32.u64 %0, t; }" : "=r"(a) : "l"(p));
    return a;
}

#define LDSM4(r, addr)                                                          \
    asm volatile("ldmatrix.sync.aligned.m8n8.x4.shared.b16 {%0,%1,%2,%3}, [%4];" \
        : "=r"((r)[0]), "=r"((r)[1]), "=r"((r)[2]), "=r"((r)[3]) : "r"(addr))

static __device__ __forceinline__ void mma_tf32(float* c, uint32_t a0, uint32_t a1,
                                                uint32_t a2, uint32_t a3,
                                                uint32_t b0, uint32_t b1) {
    asm volatile(
        "mma.sync.aligned.m16n8k8.row.col.f32.tf32.tf32.f32 "
        "{%0,%1,%2,%3}, {%4,%5,%6,%7}, {%8,%9}, {%0,%1,%2,%3};"
        : "+f"(c[0]), "+f"(c[1]), "+f"(c[2]), "+f"(c[3])
        : "r"(a0), "r"(a1), "r"(a2), "r"(a3), "r"(b0), "r"(b1));
}

__global__ __launch_bounds__(NTHREADS, 1)
void nhconv_ldsm(const float* __restrict__ x,
                 const int* __restrict__ adjc,
                 const float* __restrict__ bias,
                 float* __restrict__ out,
                 int Nn, int nwt)
{
    extern __shared__ char smem[];
    const uint32_t sbase = smem_u32(smem);
    const int tid  = threadIdx.x;
    const int lane = tid & 31;
    const int w    = tid >> 5;

    // ---- stage all 9 W tiles, swizzled: byte = k*16384 + o*256 + ((c^(o&7))<<4)
    for (int q = tid; q < KNBR * FDIM * 16; q += NTHREADS) {
        int k = q >> 10, o = (q >> 4) & 63, c = q & 15;
        float4 v = reinterpret_cast<const float4*>(g_Wt)[q];
        *reinterpret_cast<float4*>(smem + k * 16384 + o * 256 + ((c ^ (o & 7)) << 4)) = v;
    }
    __syncthreads();

    const uint32_t wB   = sbase;                    // W base
    const uint32_t wbuf = sbase + W_BYTES + w * ABUF;

    // gather-role constants: lane covers granule lr8 of rows rq+4i
    const int lr8 = lane & 7;
    const int rq  = lane >> 3;
    const uint32_t swz0 = (uint32_t)((lr8 ^ rq) << 4);
    const uint32_t swz1 = (uint32_t)((lr8 ^ (rq + 4)) << 4);

    // ldmatrix-role constants
    const int lr      = lane & 7;
    const int grp     = lane >> 3;          // 0..3
    const int halfsel = grp & 1;            // +16B
    const int rhi     = (grp >> 1) << 3;    // +8 rows
    const uint32_t rowAbyte = (uint32_t)((rhi + lr) * 128);
    const uint32_t rowBbyte = (uint32_t)((rhi + lr) * 256);
    uint32_t gA[4], gB[8];
#pragma unroll
    for (int s = 0; s < 4; s++) gA[s] = (uint32_t)(((2 * s + halfsel) ^ lr) << 4);
#pragma unroll
    for (int s = 0; s < 8; s++) gB[s] = (uint32_t)(((2 * s + halfsel) ^ lr) << 4);

    // bias fragment: cols 8j + 2*(lane&3)
    const int tig = lane & 3;
    float2 bj[8];
#pragma unroll
    for (int j = 0; j < 8; j++)
        bj[j] = *reinterpret_cast<const float2*>(bias + 8 * j + 2 * tig);

    float acc[2][8][4];
#pragma unroll
    for (int t = 0; t < 2; t++)
#pragma unroll
        for (int j = 0; j < 8; j++)
#pragma unroll
            for (int r = 0; r < 4; r++) acc[t][j][r] = 0.0f;

    const int gw      = blockIdx.x * WARPS + w;
    const int wstride = gridDim.x * WARPS;

    for (int wt = gw; wt < nwt; wt += wstride) {
        const long long m0 = (long long)wt * WROWS;
        const int b  = (int)(m0 / Nn);
        const int n0 = (int)(m0 - (long long)b * Nn);
        const float* xb = x + (size_t)b * Nn * FDIM;
        const int* arow = adjc + (size_t)n0 * KNBR;

        int idx[8];
#pragma unroll
        for (int i = 0; i < 8; i++) idx[i] = arow[(rq + 4 * i) * KNBR];
        float4 G[8];
#pragma unroll
        for (int i = 0; i < 8; i++)
            G[i] = *reinterpret_cast<const float4*>(xb + (size_t)idx[i] * FDIM + lr8 * 4);

        int p = 0;
#pragma unroll 1
        for (int k = 0; k < KNBR; k++) {
            const uint32_t wk = wB + k * 16384;
#pragma unroll
            for (int h = 0; h < 2; h++) {
                const uint32_t stage = wbuf + p * 4096;
                // store stage (raw fp32 bits; mma HW truncates to tf32)
#pragma unroll
                for (int i = 0; i < 8; i++) {
                    uint32_t a = stage + (rq + 4 * i) * 128 + ((i & 1) ? swz1 : swz0);
                    asm volatile("st.shared.v4.b32 [%0], {%1,%2,%3,%4};"
                        :: "r"(a),
                           "r"(__float_as_uint(G[i].x)), "r"(__float_as_uint(G[i].y)),
                           "r"(__float_as_uint(G[i].z)), "r"(__float_as_uint(G[i].w))
                        : "memory");
                }
                __syncwarp();

                // prefetch next half-stage
                if (h == 0) {
#pragma unroll
                    for (int i = 0; i < 8; i++)
                        G[i] = *reinterpret_cast<const float4*>(
                            xb + (size_t)idx[i] * FDIM + 32 + lr8 * 4);
                } else if (k < KNBR - 1) {
#pragma unroll
                    for (int i = 0; i < 8; i++) idx[i] = arow[(rq + 4 * i) * KNBR + k + 1];
#pragma unroll
                    for (int i = 0; i < 8; i++)
                        G[i] = *reinterpret_cast<const float4*>(
                            xb + (size_t)idx[i] * FDIM + lr8 * 4);
                }

                // compute 4 k-steps on stage
#pragma unroll
                for (int sl = 0; sl < 4; sl++) {
                    const int s = h * 4 + sl;
                    uint32_t rA0[4], rA1[4];
                    LDSM4(rA0, stage + rowAbyte + gA[sl]);
                    LDSM4(rA1, stage + 2048 + rowAbyte + gA[sl]);
#pragma unroll
                    for (int pq = 0; pq < 4; pq++) {
                        uint32_t rBv[4];
                        LDSM4(rBv, wk + pq * 4096 + rowBbyte + gB[s]);
                        mma_tf32(acc[0][2 * pq],     rA0[0], rA0[2], rA0[1], rA0[3], rBv[0], rBv[1]);
                        mma_tf32(acc[1][2 * pq],     rA1[0], rA1[2], rA1[1], rA1[3], rBv[0], rBv[1]);
                        mma_tf32(acc[0][2 * pq + 1], rA0[0], rA0[2], rA0[1], rA0[3], rBv[2], rBv[3]);
                        mma_tf32(acc[1][2 * pq + 1], rA1[0], rA1[2], rA1[1], rA1[3], rBv[2], rBv[3]);
                    }
                }
                p ^= 1;
            }
        }

        // epilogue: bias + store, zero acc
        const int g = lane >> 2;
#pragma unroll
        for (int t = 0; t < 2; t++) {
            float* r0 = out + (size_t)(m0 + t * 16 + g) * FDIM;
            float* r1 = r0 + 8 * FDIM;
#pragma unroll
            for (int j = 0; j < 8; j++) {
                int col = 8 * j + 2 * tig;
                float2 o0 = { acc[t][j][0] + bj[j].x, acc[t][j][1] + bj[j].y };
                float2 o1 = { acc[t][j][2] + bj[j].x, acc[t][j][3] + bj[j].y };
                *reinterpret_cast<float2*>(r0 + col) = o0;
                *reinterpret_cast<float2*>(r1 + col) = o1;
                acc[t][j][0] = 0.f; acc[t][j][1] = 0.f;
                acc[t][j][2] = 0.f; acc[t][j][3] = 0.f;
            }
        }
    }
}

extern "C" void kernel_launch(void* const* d_in, const int* in_sizes, int n_in,
                              void* d_out, int out_size)
{
    const float* x    = (const float*)d_in[0];   // (B, N, 64) fp32
    const int*   adjc = (const int*)d_in[1];     // (N, 9) int32
    const float* W    = (const float*)d_in[2];   // (9, 64, 64) fp32
    const float* bias = (const float*)d_in[3];   // (64,) fp32
    float*       out  = (float*)d_out;

    const int Nn = in_sizes[1] / KNBR;
    const long long M = (long long)out_size / FDIM;
    const int nwt = (int)(M / WROWS);            // 12288 warp-tiles

    cudaFuncSetAttribute(nhconv_ldsm, cudaFuncAttributeMaxDynamicSharedMemorySize, SMEM_TOTAL);

    int nsm = 148;
    cudaDeviceGetAttribute(&nsm, cudaDevAttrMultiProcessorCount, 0);

    prep_W<<<(KNBR * FDIM * FDIM + 255) / 256, 256>>>(W);
    nhconv_ldsm<<<nsm, NTHREADS, SMEM_TOTAL>>>(x, adjc, bias, out, Nn, nwt);
}

// round 7
// speedup vs baseline: 7.5625x; 1.1967x over previous
#include <cuda_runtime.h>
#include <cstdint>

// NHConv via tf32 mma.sync m16n8k8.
// out[b,n,o] = sum_{k,f} x[b, adjc[n,k], f] * W[k,f,o] + bias[o]
// Warp tile: 48 M-rows x 64 N-cols (3 m16 tiles), K' = 576.
// A: cp.async gather -> per-warp quarter-k stages (48 rows x 64B, ping/pong),
//    ldmatrix fragments, granule swizzle g' = (g + (row>>1)) & 3.
// B: W (tf32-RN, [k][o][f]) resident in smem, ldmatrix.x4. Persistent grid.
// A unrounded (mma truncates); W pre-rounded RN.

#define KNBR   9
#define FDIM   64
#define MW     48
#define WARPS  8
#define NTHREADS 256

#define W_BYTES (KNBR * FDIM * FDIM * 4)      // 147456
#define QSTG   3072                            // 48 rows * 64 B
#define ABUF   (2 * QSTG)                      // 6144 per warp
#define SMEM_TOTAL (W_BYTES + WARPS * ABUF)    // 196608

__device__ float g_Wt[KNBR * FDIM * FDIM];     // [k][o][f], tf32-RN

__global__ void prep_W(const float* __restrict__ W) {
    int idx = blockIdx.x * 256 + threadIdx.x;
    if (idx >= KNBR * FDIM * FDIM) return;
    int k = idx >> 12, rem = idx & 4095, o = rem >> 6, f = rem & 63;
    float v = W[(k << 12) + (f << 6) + o];
    uint32_t t;
    asm("cvt.rna.tf32.f32 %0, %1;" : "=r"(t) : "f"(v));
    g_Wt[idx] = __uint_as_float(t);
}

static __device__ __forceinline__ uint32_t smem_u32(const void* p) {
    uint32_t a;
    asm("{ .reg .u64 t; cvta.to.shared.u64 t, %1; cvt.u32.u64 %0, t; }" : "=r"(a) : "l"(p));
    return a;
}

#define LDSM4(r, addr)                                                          \
    asm volatile("ldmatrix.sync.aligned.m8n8.x4.shared.b16 {%0,%1,%2,%3}, [%4];" \
        : "=r"((r)[0]), "=r"((r)[1]), "=r"((r)[2]), "=r"((r)[3]) : "r"(addr))

static __device__ __forceinline__ void mma_tf32(float* c, uint32_t a0, uint32_t a1,
                                                uint32_t a2, uint32_t a3,
                                                uint32_t b0, uint32_t b1) {
    asm volatile(
        "mma.sync.aligned.m16n8k8.row.col.f32.tf32.tf32.f32 "
        "{%0,%1,%2,%3}, {%4,%5,%6,%7}, {%8,%9}, {%0,%1,%2,%3};"
        : "+f"(c[0]), "+f"(c[1]), "+f"(c[2]), "+f"(c[3])
        : "r"(a0), "r"(a1), "r"(a2), "r"(a3), "r"(b0), "r"(b1));
}

// issue one quarter-k gather (16 f-elems, 48 rows) into stage DSTB; 1 commit group
#define ISSUE_Q(DSTB, QQ) do {                                                   \
    _Pragma("unroll")                                                            \
    for (int _i = 0; _i < 6; _i++) {                                             \
        uint32_t _dst = (DSTB) + (uint32_t)((gr + 8 * _i) * 64) + gsw;           \
        const char* _src = xbc + (size_t)(uint32_t)idx[_i] * 256                 \
                           + (QQ) * 64 + gg * 16;                                \
        asm volatile("cp.async.cg.shared.global [%0], [%1], 16;"                 \
            :: "r"(_dst), "l"(_src) : "memory");                                 \
    }                                                                            \
    asm volatile("cp.async.commit_group;" ::: "memory");                         \
} while (0)

#define WAITG(N) do {                                                            \
    asm volatile("cp.async.wait_group %0;" :: "n"(N) : "memory");                \
    __syncwarp();                                                                \
} while (0)

// compute 2 k-steps of quarter Q from STAGE against W tile at WK
#define COMPUTE_Q(STAGE, WK, Q) do {                                             \
    _Pragma("unroll")                                                            \
    for (int _s = 0; _s < 2; _s++) {                                             \
        uint32_t rA0[4], rA1[4], rA2[4];                                         \
        LDSM4(rA0, (STAGE) + rowA + gAq[_s]);                                    \
        LDSM4(rA1, (STAGE) + 1024 + rowA + gAq[_s]);                             \
        LDSM4(rA2, (STAGE) + 2048 + rowA + gAq[_s]);                             \
        const int _sg = (Q) * 2 + _s;                                            \
        _Pragma("unroll")                                                        \
        for (int _pq = 0; _pq < 4; _pq++) {                                      \
            uint32_t rB[4];                                                      \
            LDSM4(rB, (WK) + _pq * 4096 + rowB + gB[_sg]);                       \
            mma_tf32(acc[0][2*_pq],   rA0[0], rA0[2], rA0[1], rA0[3], rB[0], rB[1]); \
            mma_tf32(acc[1][2*_pq],   rA1[0], rA1[2], rA1[1], rA1[3], rB[0], rB[1]); \
            mma_tf32(acc[2][2*_pq],   rA2[0], rA2[2], rA2[1], rA2[3], rB[0], rB[1]); \
            mma_tf32(acc[0][2*_pq+1], rA0[0], rA0[2], rA0[1], rA0[3], rB[2], rB[3]); \
            mma_tf32(acc[1][2*_pq+1], rA1[0], rA1[2], rA1[1], rA1[3], rB[2], rB[3]); \
            mma_tf32(acc[2][2*_pq+1], rA2[0], rA2[2], rA2[1], rA2[3], rB[2], rB[3]); \
        }                                                                        \
    }                                                                            \
} while (0)

__global__ __launch_bounds__(NTHREADS, 1)
void nhconv_cp(const float* __restrict__ x,
               const int* __restrict__ adjc,
               const float* __restrict__ bias,
               float* __restrict__ out,
               int Nn, int nwt)
{
    extern __shared__ char smem[];
    const uint32_t sbase = smem_u32(smem);
    const int tid  = threadIdx.x;
    const int lane = tid & 31;
    const int w    = tid >> 5;

    // stage all 9 W tiles, swizzled: byte = k*16384 + o*256 + ((c ^ (o&7))<<4)
    for (int q = tid; q < KNBR * FDIM * 16; q += NTHREADS) {
        int k = q >> 10, o = (q >> 4) & 63, c = q & 15;
        float4 v = reinterpret_cast<const float4*>(g_Wt)[q];
        *reinterpret_cast<float4*>(smem + k * 16384 + o * 256 + ((c ^ (o & 7)) << 4)) = v;
    }
    __syncthreads();

    const uint32_t wB   = sbase;
    const uint32_t wbuf = sbase + W_BYTES + w * ABUF;   // stage 0; stage 1 = +QSTG

    // gather roles: lane covers rows gr+8i (i=0..5), f-chunk gg (16B)
    const int gr = lane >> 2;
    const int gg = lane & 3;
    const uint32_t gsw = (uint32_t)(((gg + (gr >> 1)) & 3) << 4);

    // ldmatrix roles
    const int lr      = lane & 7;
    const int grp     = lane >> 3;
    const int halfsel = grp & 1;
    const int rhi     = (grp >> 1) << 3;
    const uint32_t rowA = (uint32_t)((rhi + lr) * 64);
    const uint32_t rowB = (uint32_t)((rhi + lr) * 256);
    uint32_t gAq[2], gB[8];
#pragma unroll
    for (int s = 0; s < 2; s++)
        gAq[s] = (uint32_t)((((2 * s + halfsel) + (lr >> 1)) & 3) << 4);
#pragma unroll
    for (int s = 0; s < 8; s++)
        gB[s] = (uint32_t)(((2 * s + halfsel) ^ lr) << 4);

    // bias fragment
    const int tig = lane & 3;
    float2 bj[8];
#pragma unroll
    for (int j = 0; j < 8; j++)
        bj[j] = *reinterpret_cast<const float2*>(bias + 8 * j + 2 * tig);

    float acc[3][8][4];
#pragma unroll
    for (int t = 0; t < 3; t++)
#pragma unroll
        for (int j = 0; j < 8; j++)
#pragma unroll
            for (int r = 0; r < 4; r++) acc[t][j][r] = 0.0f;

    const int gw      = blockIdx.x * WARPS + w;
    const int wstride = gridDim.x * WARPS;

    for (int wt = gw; wt < nwt; wt += wstride) {
        const long long m0 = (long long)wt * MW;
        const int b  = (int)(m0 / Nn);
        const int n0 = (int)(m0 - (long long)b * Nn);
        const char* xbc = reinterpret_cast<const char*>(x + (size_t)b * Nn * FDIM);
        const int* arow = adjc + (size_t)n0 * KNBR;

        int idx[6];
#pragma unroll
        for (int i = 0; i < 6; i++) idx[i] = arow[(gr + 8 * i) * KNBR];

        ISSUE_Q(wbuf, 0);                         // quarter 0 -> buf0

#pragma unroll 1
        for (int k = 0; k < KNBR; k++) {
            const uint32_t wk = wB + (k << 14);

            ISSUE_Q(wbuf + QSTG, 1);              // q1 -> buf1
            WAITG(1);
            COMPUTE_Q(wbuf, wk, 0);

            ISSUE_Q(wbuf, 2);                     // q2 -> buf0
            WAITG(1);
            COMPUTE_Q(wbuf + QSTG, wk, 1);

            ISSUE_Q(wbuf + QSTG, 3);              // q3 -> buf1
            WAITG(1);
            COMPUTE_Q(wbuf, wk, 2);

            if (k < KNBR - 1) {
#pragma unroll
                for (int i = 0; i < 6; i++) idx[i] = arow[(gr + 8 * i) * KNBR + k + 1];
                ISSUE_Q(wbuf, 0);                 // next k's q0 -> buf0
                WAITG(1);
            } else {
                WAITG(0);
            }
            COMPUTE_Q(wbuf + QSTG, wk, 3);
        }

        // epilogue: bias + store, zero acc
        const int g = lane >> 2;
#pragma unroll
        for (int t = 0; t < 3; t++) {
            float* r0 = out + (size_t)(m0 + t * 16 + g) * FDIM;
            float* r1 = r0 + 8 * FDIM;
#pragma unroll
            for (int j = 0; j < 8; j++) {
                int col = 8 * j + 2 * tig;
                float2 o0 = { acc[t][j][0] + bj[j].x, acc[t][j][1] + bj[j].y };
                float2 o1 = { acc[t][j][2] + bj[j].x, acc[t][j][3] + bj[j].y };
                *reinterpret_cast<float2*>(r0 + col) = o0;
                *reinterpret_cast<float2*>(r1 + col) = o1;
                acc[t][j][0] = 0.f; acc[t][j][1] = 0.f;
                acc[t][j][2] = 0.f; acc[t][j][3] = 0.f;
            }
        }
    }
}

extern "C" void kernel_launch(void* const* d_in, const int* in_sizes, int n_in,
                              void* d_out, int out_size)
{
    const float* x    = (const float*)d_in[0];   // (B, N, 64) fp32
    const int*   adjc = (const int*)d_in[1];     // (N, 9) int32
    const float* W    = (const float*)d_in[2];   // (9, 64, 64) fp32
    const float* bias = (const float*)d_in[3];   // (64,) fp32
    float*       out  = (float*)d_out;

    const int Nn = in_sizes[1] / KNBR;
    const long long M = (long long)out_size / FDIM;
    const int nwt = (int)(M / MW);               // 8192 warp-tiles

    cudaFuncSetAttribute(nhconv_cp, cudaFuncAttributeMaxDynamicSharedMemorySize, SMEM_TOTAL);

    int nsm = 148;
    cudaDeviceGetAttribute(&nsm, cudaDevAttrMultiProcessorCount, 0);

    prep_W<<<(KNBR * FDIM * FDIM + 255) / 256, 256>>>(W);
    nhconv_cp<<<nsm, NTHREADS, SMEM_TOTAL>>>(x, adjc, bias, out, Nn, nwt);
}